// round 1
// baseline (speedup 1.0000x reference)
#include <cuda_runtime.h>

#define N_ATOMS 1024
#define NFEAT   80
#define NIRR    48
#define K3      1270
#define K2      24
#define K1      3
#define M3      (NIRR*NIRR*NIRR)   // 110592
#define PQ      (NIRR*NIRR)        // 2304

typedef unsigned long long ull;

// Scratch (device globals — no allocation allowed in kernel_launch)
__device__ float2 g_UW3[(size_t)NFEAT * M3];      // duplicated packed {v,v}: 70.8 MB
__device__ float  g_C2W[NFEAT * PQ];
__device__ float  g_C1W[NFEAT * NIRR];

// ---- packed f32x2 helpers (Blackwell sm_103a) ----
__device__ __forceinline__ ull pack2(float x, float y) {
    ull r; asm("mov.b64 %0, {%1,%2};" : "=l"(r) : "f"(x), "f"(y)); return r;
}
__device__ __forceinline__ void unpack2(ull v, float &x, float &y) {
    asm("mov.b64 {%0,%1}, %2;" : "=f"(x), "=f"(y) : "l"(v));
}
__device__ __forceinline__ ull fma2(ull a, ull b, ull c) {
    ull d; asm("fma.rn.f32x2 %0, %1, %2, %3;" : "=l"(d) : "l"(a), "l"(b), "l"(c)); return d;
}
__device__ __forceinline__ ull add2(ull a, ull b) {
    ull d; asm("add.rn.f32x2 %0, %1, %2;" : "=l"(d) : "l"(a), "l"(b)); return d;
}

// ============================================================
// Kernel 1: C2W[c,p,q] = sum_k U2[p,q,k] W2[k,c];  C1W[c,p] = sum_k U1[p,k] W1[k,c]
// ============================================================
__global__ __launch_bounds__(256) void k_small(
    const float* __restrict__ U2, const float* __restrict__ W2,
    const float* __restrict__ U1, const float* __restrict__ W1)
{
    int c = blockIdx.x;
    int t = threadIdx.x;
    __shared__ float w2[K2];
    __shared__ float w1[K1];
    if (t < K2) w2[t] = W2[t * NFEAT + c];
    if (t < K1) w1[t] = W1[t * NFEAT + c];
    __syncthreads();
    for (int pq = t; pq < PQ; pq += 256) {
        float s = 0.f;
        #pragma unroll
        for (int k = 0; k < K2; k++) s += U2[pq * K2 + k] * w2[k];
        g_C2W[c * PQ + pq] = s;
    }
    if (t < NIRR) {
        float s = 0.f;
        #pragma unroll
        for (int k = 0; k < K1; k++) s += U1[t * K1 + k] * w1[k];
        g_C1W[c * NIRR + t] = s;
    }
}

// ============================================================
// Kernel 2: UW3[c, m] = sum_k U3_flat[m, k] * W3[k, c]   (m = (p*48+q)*48+i)
// GEMM M=110592, N=80, K=1270. f32x2 over channel pairs. Output duplicated {v,v}.
// Block: 128 m-rows x all 80 c. 256 threads = 32(ty, m) x 8(tx, c-group).
// ============================================================
#define BK 32
__global__ __launch_bounds__(256) void k_gemm1(
    const float* __restrict__ U3, const float* __restrict__ W3)
{
    __shared__ float  As[BK][128];
    __shared__ float2 Bs[BK][40];

    int t  = threadIdx.x;
    int ty = t & 31;        // m lane
    int tx = t >> 5;        // c group (0..7) — constant within a warp
    int m0 = blockIdx.x * 128;

    ull acc[4][5];
    #pragma unroll
    for (int j = 0; j < 4; j++)
        #pragma unroll
        for (int u = 0; u < 5; u++) acc[j][u] = 0ull;

    int lm = t >> 3;          // 0..31 (A-load row group)
    int lk = (t & 7) * 4;     // 0..28 (A-load k offset)

    for (int kc = 0; kc < K3; kc += BK) {
        // --- load A tile: U3[m0+mm, kc+kk] -> As[kk][mm]
        #pragma unroll
        for (int r = 0; r < 4; r++) {
            int mm = lm + 32 * r;
            const float* src = U3 + (size_t)(m0 + mm) * K3 + kc + lk;
            float v[4];
            if (kc + lk + 3 < K3) {
                float2 a = *(const float2*)src;
                float2 b = *(const float2*)(src + 2);
                v[0] = a.x; v[1] = a.y; v[2] = b.x; v[3] = b.y;
            } else {
                #pragma unroll
                for (int e = 0; e < 4; e++) v[e] = (kc + lk + e < K3) ? src[e] : 0.f;
            }
            #pragma unroll
            for (int e = 0; e < 4; e++) As[lk + e][mm] = v[e];
        }
        // --- load B tile: W3[kc+kk, 2cp:2cp+2] -> Bs[kk][cp]
        #pragma unroll
        for (int j = 0; j < 5; j++) {
            int idx = t + 256 * j;          // 0..1279
            int kk = idx / 40, cp = idx % 40;
            float2 b = make_float2(0.f, 0.f);
            if (kc + kk < K3) b = *(const float2*)(W3 + (size_t)(kc + kk) * NFEAT + 2 * cp);
            Bs[kk][cp] = b;
        }
        __syncthreads();

        #pragma unroll 8
        for (int kk = 0; kk < BK; kk++) {
            ull b2[5];
            #pragma unroll
            for (int u = 0; u < 5; u++) {
                float2 b = Bs[kk][tx + 8 * u];   // warp-uniform broadcast
                b2[u] = pack2(b.x, b.y);
            }
            #pragma unroll
            for (int j = 0; j < 4; j++) {
                float a = As[kk][ty + 32 * j];
                ull a2 = pack2(a, a);
                #pragma unroll
                for (int u = 0; u < 5; u++) acc[j][u] = fma2(a2, b2[u], acc[j][u]);
            }
        }
        __syncthreads();
    }

    // --- store duplicated: g_UW3[c][m] = {v,v}
    #pragma unroll
    for (int j = 0; j < 4; j++) {
        int m = m0 + ty + 32 * j;   // warp lanes -> 32 consecutive m (coalesced)
        #pragma unroll
        for (int u = 0; u < 5; u++) {
            int c0 = 2 * (tx + 8 * u);
            float lo, hi; unpack2(acc[j][u], lo, hi);
            g_UW3[(size_t)c0 * M3 + m]       = make_float2(lo, lo);
            g_UW3[(size_t)(c0 + 1) * M3 + m] = make_float2(hi, hi);
        }
    }
}

// ============================================================
// Kernel 3: out[n,c] = sum_p nf_p ( C1W + sum_q nf_q ( C2W + sum_i UW3[c,p,q,i] nf_i ) )
// Block: fixed c, 128 threads x 2 atoms (packed f32x2). grid (4, 80).
// ============================================================
#define TPB 128
#define SMEM_MAIN (PQ*8 + TPB*49*8 + 64*4)   // uw(18432) + nfsm(50176) + c2sm pad

__global__ __launch_bounds__(TPB) void k_main(
    const float* __restrict__ nf, float* __restrict__ out)
{
    extern __shared__ char smem_raw[];
    float2* uw   = (float2*)smem_raw;                          // [48][48] dup-packed
    ull*    nfsm = (ull*)(smem_raw + PQ * 8);                  // [128][49]
    float*  c2sm = (float*)(smem_raw + PQ * 8 + TPB * 49 * 8); // [48]

    int t = threadIdx.x;
    int c = blockIdx.y;
    int nA = (blockIdx.x * TPB + t) * 2;
    int nB = nA + 1;

    const float* fa = nf + (size_t)nA * (NFEAT * NIRR) + c * NIRR;
    const float* fb = nf + (size_t)nB * (NFEAT * NIRR) + c * NIRR;

    ull nf2[NIRR];
    ull* myrow = nfsm + t * 49;
    #pragma unroll
    for (int i4 = 0; i4 < 12; i4++) {
        float4 a = *(const float4*)(fa + 4 * i4);
        float4 b = *(const float4*)(fb + 4 * i4);
        nf2[4*i4+0] = pack2(a.x, b.x);
        nf2[4*i4+1] = pack2(a.y, b.y);
        nf2[4*i4+2] = pack2(a.z, b.z);
        nf2[4*i4+3] = pack2(a.w, b.w);
        myrow[4*i4+0] = nf2[4*i4+0];
        myrow[4*i4+1] = nf2[4*i4+1];
        myrow[4*i4+2] = nf2[4*i4+2];
        myrow[4*i4+3] = nf2[4*i4+3];
    }

    const float4* uwc = (const float4*)(g_UW3 + (size_t)c * M3);
    ull acc = 0ull;

    for (int p = 0; p < NIRR; p++) {
        __syncthreads();
        // stage UW3 row [p][*][*]: 1152 float4
        const float4* src = uwc + (size_t)p * (PQ / 2);
        float4* dst = (float4*)uw;
        #pragma unroll
        for (int j = 0; j < 9; j++) dst[t + TPB * j] = src[t + TPB * j];
        if (t < NIRR) c2sm[t] = g_C2W[c * PQ + p * NIRR + t];
        __syncthreads();

        float c1 = g_C1W[c * NIRR + p];
        ull tp = pack2(c1, c1);

        for (int q = 0; q < NIRR; q++) {
            float c2v = c2sm[q];
            ull s0 = pack2(c2v, c2v), s1 = 0ull, s2 = 0ull, s3 = 0ull;
            const ulonglong2* uq = (const ulonglong2*)(uw + q * NIRR);
            #pragma unroll
            for (int ii = 0; ii < 12; ii++) {
                ulonglong2 u0 = uq[2 * ii];
                ulonglong2 u1 = uq[2 * ii + 1];
                s0 = fma2(nf2[4*ii+0], u0.x, s0);
                s1 = fma2(nf2[4*ii+1], u0.y, s1);
                s2 = fma2(nf2[4*ii+2], u1.x, s2);
                s3 = fma2(nf2[4*ii+3], u1.y, s3);
            }
            ull s = add2(add2(s0, s1), add2(s2, s3));
            tp = fma2(myrow[q], s, tp);
        }
        acc = fma2(myrow[p], tp, acc);
    }

    float oa, ob; unpack2(acc, oa, ob);
    out[(size_t)nA * NFEAT + c] = oa;
    out[(size_t)nB * NFEAT + c] = ob;
}

// ============================================================
extern "C" void kernel_launch(void* const* d_in, const int* in_sizes, int n_in,
                              void* d_out, int out_size)
{
    const float* nf = (const float*)d_in[0];
    const float* U3 = (const float*)d_in[1];
    const float* U2 = (const float*)d_in[2];
    const float* U1 = (const float*)d_in[3];
    const float* W3 = (const float*)d_in[4];
    const float* W2 = (const float*)d_in[5];
    const float* W1 = (const float*)d_in[6];
    float* out = (float*)d_out;

    cudaFuncSetAttribute(k_main, cudaFuncAttributeMaxDynamicSharedMemorySize, SMEM_MAIN);

    k_small<<<NFEAT, 256>>>(U2, W2, U1, W1);
    k_gemm1<<<M3 / 128, 256>>>(U3, W3);
    dim3 g(N_ATOMS / (2 * TPB), NFEAT);
    k_main<<<g, TPB, SMEM_MAIN>>>(nf, out);
}